// round 1
// baseline (speedup 1.0000x reference)
#include <cuda_runtime.h>
#include <math.h>

typedef unsigned long long u64;
#define DINL __device__ __forceinline__

// ---------------- scratch (no allocations allowed) ----------------
static __device__ float  g_feats[4*4*2048*64];   // [b][h][n][64]  8 MB
static __device__ float  g_s_self[4*4*2048];
static __device__ float  g_s_neigh[4*4*2048];
static __device__ float4 g_sn4[4*2048];          // [b][j] -> {h0,h1,h2,h3}
static __device__ float  g_m[4*4*2048];
static __device__ float  g_invZ[4*4*2048];
static __device__ float  g_psum[256];
static __device__ int    g_pcd[256];
static __device__ int    g_pca[256];

// ---------------- f32x2 helpers ----------------
DINL u64 pk2(float a, float b){ u64 r; asm("mov.b64 %0, {%1, %2};" : "=l"(r) : "f"(a), "f"(b)); return r; }
DINL void fma2(u64& d, u64 a, u64 b){ asm("fma.rn.f32x2 %0, %1, %2, %0;" : "+l"(d) : "l"(a), "l"(b)); }
DINL float2 upk(u64 v){ float2 r; asm("mov.b64 {%0, %1}, %2;" : "=f"(r.x), "=f"(r.y) : "l"(v)); return r; }

// ================= kernel 1: feats = x @ W[h] =================
// grid (32, 4, 4) = (ntile64, h, b), 256 threads
__global__ void __launch_bounds__(256) k_feats(const float* __restrict__ x,
                                               const float* __restrict__ W){
    __shared__ float Ws[64*64];
    __shared__ float Xs[64*64];
    int b = blockIdx.z, h = blockIdx.y, it = blockIdx.x, t = threadIdx.x;
    const float* wsrc = W + h*4096;
    const float* xsrc = x + (b*2048 + it*64)*64;
    for (int e = t; e < 4096; e += 256){ Ws[e] = wsrc[e]; Xs[e] = xsrc[e]; }
    __syncthreads();
    int k = t & 63, rg = t >> 6;            // rg 0..3 -> rows rg*16..+15
    float acc[16];
    #pragma unroll
    for (int r = 0; r < 16; r++) acc[r] = 0.f;
    #pragma unroll 8
    for (int f = 0; f < 64; f++){
        float wf = Ws[f*64 + k];
        #pragma unroll
        for (int r = 0; r < 16; r++) acc[r] += Xs[(rg*16 + r)*64 + f] * wf;
    }
    float* fo = g_feats + ((b*4 + h)*2048 + it*64)*64;
    #pragma unroll
    for (int r = 0; r < 16; r++) fo[(rg*16 + r)*64 + k] = acc[r];
}

// ================= kernel 2: attention logit scalars =================
// warp per (b,h,n) row; grid 4096 blocks x 256
__global__ void __launch_bounds__(256) k_scores(const float* __restrict__ a_self,
                                                const float* __restrict__ a_neigh){
    int t = threadIdx.x, w = t >> 5, lane = t & 31;
    int row = blockIdx.x*8 + w;             // 0..32767 over (b,h,n)
    int bh = row >> 11, h = bh & 3, b = bh >> 2, i = row & 2047;
    const float* fr = g_feats + row*64;
    float f0 = fr[lane], f1 = fr[lane + 32];
    float ss = f0*a_self[h*64 + lane]  + f1*a_self[h*64 + lane + 32];
    float sn = f0*a_neigh[h*64 + lane] + f1*a_neigh[h*64 + lane + 32];
    #pragma unroll
    for (int o = 16; o > 0; o >>= 1){
        ss += __shfl_xor_sync(0xffffffffu, ss, o);
        sn += __shfl_xor_sync(0xffffffffu, sn, o);
    }
    if (lane == 0){
        g_s_self[row]  = ss;
        g_s_neigh[row] = sn;
        ((float*)(g_sn4 + b*2048 + i))[h] = sn;
    }
}

// ================= kernel 3: row max + sum-exp (all 4 heads / pass) =================
DINL void onl_upd(float& m, float& z, float sc){
    if (sc > m){ z = z*__expf(m - sc) + 1.f; m = sc; } else z += __expf(sc - m);
}
DINL void onl_merge(float& m, float& z, int o){
    float mo = __shfl_xor_sync(0xffffffffu, m, o);
    float zo = __shfl_xor_sync(0xffffffffu, z, o);
    float mn = fmaxf(m, mo);
    z = z*__expf(m - mn) + zo*__expf(mo - mn);
    m = mn;
}
// grid 1024 blocks x 256 (warp per (b,i) row)
__global__ void __launch_bounds__(256) k_mz(const float* __restrict__ mask){
    int t = threadIdx.x, w = t >> 5, lane = t & 31;
    int r = blockIdx.x*8 + w;               // 0..8191 over (b,i)
    int b = r >> 11, i = r & 2047;
    float ss0 = g_s_self[(b*4+0)*2048 + i];
    float ss1 = g_s_self[(b*4+1)*2048 + i];
    float ss2 = g_s_self[(b*4+2)*2048 + i];
    float ss3 = g_s_self[(b*4+3)*2048 + i];
    const float*  mrow = mask + (b*2048 + i)*2048;
    const float4* sn4  = g_sn4 + b*2048;
    const float NEGINF = __int_as_float(0xff800000);
    float m0=NEGINF, m1=NEGINF, m2=NEGINF, m3=NEGINF;
    float z0=0.f, z1=0.f, z2=0.f, z3=0.f;
    for (int j = lane; j < 2048; j += 32){
        float mk = mrow[j];
        float4 sn = sn4[j];
        float sc;
        sc = ss0 + sn.x; sc = sc > 0.f ? sc : 0.2f*sc; sc += mk; onl_upd(m0, z0, sc);
        sc = ss1 + sn.y; sc = sc > 0.f ? sc : 0.2f*sc; sc += mk; onl_upd(m1, z1, sc);
        sc = ss2 + sn.z; sc = sc > 0.f ? sc : 0.2f*sc; sc += mk; onl_upd(m2, z2, sc);
        sc = ss3 + sn.w; sc = sc > 0.f ? sc : 0.2f*sc; sc += mk; onl_upd(m3, z3, sc);
    }
    #pragma unroll
    for (int o = 16; o > 0; o >>= 1){
        onl_merge(m0, z0, o); onl_merge(m1, z1, o);
        onl_merge(m2, z2, o); onl_merge(m3, z3, o);
    }
    if (lane == 0){
        g_m[(b*4+0)*2048 + i] = m0; g_invZ[(b*4+0)*2048 + i] = 1.f/z0;
        g_m[(b*4+1)*2048 + i] = m1; g_invZ[(b*4+1)*2048 + i] = 1.f/z1;
        g_m[(b*4+2)*2048 + i] = m2; g_invZ[(b*4+2)*2048 + i] = 1.f/z2;
        g_m[(b*4+3)*2048 + i] = m3; g_invZ[(b*4+3)*2048 + i] = 1.f/z3;
    }
}

// ================= kernel 4: P = softmax*adj ; out = P @ feats (fused epilogue) =================
// grid (16, 4, 4) = (i-tile of 128, h, b); 256 threads; thread tile 8i x 4k, f32x2 over i-pairs
__global__ void __launch_bounds__(256) k_main(const float* __restrict__ adj,
                                              const float* __restrict__ mask,
                                              const float* __restrict__ bias,
                                              float* __restrict__ out){
    __shared__ float Ps[32*130];            // [j][i], stride 130 (pad for conflicts)
    __shared__ float Fs[32*64];             // [j][k]
    __shared__ float Ss[128], Msm[128], Zsm[128];
    __shared__ float rS[256];
    __shared__ int   rD[256], rA[256];

    int b = blockIdx.z, h = blockIdx.y, it = blockIdx.x, t = threadIdx.x;
    int bh = b*4 + h;
    if (t < 128){
        int gi = it*128 + t;
        Ss[t]  = g_s_self[bh*2048 + gi];
        Msm[t] = g_m[bh*2048 + gi];
        Zsm[t] = g_invZ[bh*2048 + gi];
    }
    int kg = t & 15, ig = t >> 4;
    int k0 = kg*4,  i0 = ig*8;
    u64 acc[4][4];
    #pragma unroll
    for (int a = 0; a < 4; a++)
        #pragma unroll
        for (int c = 0; c < 4; c++) acc[a][c] = 0ull;

    int jl = t & 31, ib = t >> 5;
    float sumD = 0.f; int cntD = 0, cntA = 0;
    const float* fbase = g_feats + bh*2048*64;

    for (int jt = 0; jt < 64; jt++){
        int j0 = jt*32;
        __syncthreads();
        // ---- Phase A: compute P tile (128 x 32), gather loss stats ----
        float snj = g_s_neigh[bh*2048 + j0 + jl];
        #pragma unroll 4
        for (int p = 0; p < 16; p++){
            int i  = p*8 + ib;                       // 0..127
            int gi = it*128 + i;
            int gidx = (b*2048 + gi)*2048 + j0 + jl;
            float mk = mask[gidx];
            float aj = adj[gidx];
            float sc = Ss[i] + snj;
            sc = sc > 0.f ? sc : 0.2f*sc;
            sc += mk;
            float pd = __expf(sc - Msm[i]) * Zsm[i] * aj;
            Ps[jl*130 + i] = pd;
            sumD += fabsf(pd);
            cntD += (pd != 0.f) ? 1 : 0;
            cntA += (aj != 0.f) ? 1 : 0;
        }
        // ---- feats tile load ----
        const float* fsrc = fbase + j0*64;
        #pragma unroll
        for (int p = 0; p < 8; p++){ int e = p*256 + t; Fs[e] = fsrc[e]; }
        __syncthreads();
        // ---- Phase B: FFMA2 GEMM ----
        #pragma unroll 8
        for (int j = 0; j < 32; j++){
            float4 v = *(const float4*)&Fs[j*64 + k0];
            u64 v0 = pk2(v.x, v.x), v1 = pk2(v.y, v.y);
            u64 v2 = pk2(v.z, v.z), v3 = pk2(v.w, v.w);
            const float* pr = &Ps[j*130 + i0];
            u64 p0 = *(const u64*)(pr);
            u64 p1 = *(const u64*)(pr + 2);
            u64 p2 = *(const u64*)(pr + 4);
            u64 p3 = *(const u64*)(pr + 6);
            fma2(acc[0][0], p0, v0); fma2(acc[0][1], p0, v1); fma2(acc[0][2], p0, v2); fma2(acc[0][3], p0, v3);
            fma2(acc[1][0], p1, v0); fma2(acc[1][1], p1, v1); fma2(acc[1][2], p1, v2); fma2(acc[1][3], p1, v3);
            fma2(acc[2][0], p2, v0); fma2(acc[2][1], p2, v1); fma2(acc[2][2], p2, v2); fma2(acc[2][3], p2, v3);
            fma2(acc[3][0], p3, v0); fma2(acc[3][1], p3, v1); fma2(acc[3][2], p3, v2); fma2(acc[3][3], p3, v3);
        }
    }

    // ---- epilogue: bias + batchnorm scale + relu, write act ----
    const float SC = 0.9995003746877732f;   // 1/sqrt(1.001)
    float4 bi = *(const float4*)&bias[h*64 + k0];
    #pragma unroll
    for (int ip = 0; ip < 4; ip++){
        float2 e0 = upk(acc[ip][0]), e1 = upk(acc[ip][1]);
        float2 e2 = upk(acc[ip][2]), e3 = upk(acc[ip][3]);
        int r0 = it*128 + i0 + 2*ip;
        float4 o0, o1;
        o0.x = fmaxf((e0.x + bi.x)*SC, 0.f); o0.y = fmaxf((e1.x + bi.y)*SC, 0.f);
        o0.z = fmaxf((e2.x + bi.z)*SC, 0.f); o0.w = fmaxf((e3.x + bi.w)*SC, 0.f);
        o1.x = fmaxf((e0.y + bi.x)*SC, 0.f); o1.y = fmaxf((e1.y + bi.y)*SC, 0.f);
        o1.z = fmaxf((e2.y + bi.z)*SC, 0.f); o1.w = fmaxf((e3.y + bi.w)*SC, 0.f);
        *(float4*)&out[(b*2048 + r0    )*256 + h*64 + k0] = o0;
        *(float4*)&out[(b*2048 + r0 + 1)*256 + h*64 + k0] = o1;
    }

    // ---- deterministic block reduce of loss stats ----
    rS[t] = sumD; rD[t] = cntD; rA[t] = cntA;
    __syncthreads();
    #pragma unroll
    for (int s = 128; s > 0; s >>= 1){
        if (t < s){ rS[t] += rS[t + s]; rD[t] += rD[t + s]; rA[t] += rA[t + s]; }
        __syncthreads();
    }
    if (t == 0){
        int pb = (b*4 + h)*16 + it;
        g_psum[pb] = rS[0]; g_pcd[pb] = rD[0]; g_pca[pb] = rA[0];
    }
}

// ================= kernel 5: finalize aux losses =================
__global__ void k_loss(float* __restrict__ out){
    int b = threadIdx.x;
    if (b < 4){
        float s = 0.f; int d = 0, a = 0;
        for (int p = 0; p < 64; p++){
            int idx = b*64 + p;
            s += g_psum[idx]; d += g_pcd[idx]; a += g_pca[idx];
        }
        // u_loss[b] = (sum_{h,i} counts - 4*sum_i deg) / N   (cntA counts adj!=0 once per head)
        out[2097152 + b] = (float)(d - a) * (1.f/2048.f);
        // e_loss[b] = sum_{h,i,j} |dense| / N
        out[2097156 + b] = s * (1.f/2048.f);
    }
}

// ================= launch =================
extern "C" void kernel_launch(void* const* d_in, const int* in_sizes, int n_in,
                              void* d_out, int out_size){
    const float* x       = (const float*)d_in[0];
    const float* adj     = (const float*)d_in[1];
    const float* mask    = (const float*)d_in[2];
    const float* W       = (const float*)d_in[3];
    const float* a_self  = (const float*)d_in[4];
    const float* a_neigh = (const float*)d_in[5];
    const float* bias    = (const float*)d_in[6];
    float* out = (float*)d_out;

    k_feats <<<dim3(32, 4, 4), 256>>>(x, W);
    k_scores<<<4096, 256>>>(a_self, a_neigh);
    k_mz    <<<1024, 256>>>(mask);
    k_main  <<<dim3(16, 4, 4), 256>>>(adj, mask, bias, out);
    k_loss  <<<1, 32>>>(out);
}

// round 2
// speedup vs baseline: 1.2947x; 1.2947x over previous
#include <cuda_runtime.h>
#include <math.h>

typedef unsigned long long u64;
#define DINL __device__ __forceinline__

#define JSPLIT 4
#define OUTEL  2097152            // 4*2048*256

// ---------------- scratch (no allocations allowed) ----------------
static __device__ float  g_feats[4*4*2048*64];     // [b][h][n][64]  8 MB
static __device__ float  g_s_self[4*4*2048];
static __device__ float  g_s_neigh[4*4*2048];
static __device__ float  g_invZ[4*4*2048];
static __device__ float  g_part[JSPLIT*OUTEL];     // 33.5 MB partial outputs
static __device__ float  g_psum[1024];
static __device__ int    g_pcd[1024];
static __device__ int    g_pca[1024];

// ---------------- f32x2 helpers ----------------
DINL u64 pk2(float a, float b){ u64 r; asm("mov.b64 %0, {%1, %2};" : "=l"(r) : "f"(a), "f"(b)); return r; }
DINL void fma2(u64& d, u64 a, u64 b){ asm("fma.rn.f32x2 %0, %1, %2, %0;" : "+l"(d) : "l"(a), "l"(b)); }
DINL float2 upk(u64 v){ float2 r; asm("mov.b64 {%0, %1}, %2;" : "=f"(r.x), "=f"(r.y) : "l"(v)); return r; }

// ================= kernel 1: feats = x @ W[h] =================
// grid (32, 4, 4) = (ntile64, h, b), 256 threads
__global__ void __launch_bounds__(256) k_feats(const float* __restrict__ x,
                                               const float* __restrict__ W){
    __shared__ float Ws[64*64];
    __shared__ float Xs[64*64];
    int b = blockIdx.z, h = blockIdx.y, it = blockIdx.x, t = threadIdx.x;
    const float* wsrc = W + h*4096;
    const float* xsrc = x + (b*2048 + it*64)*64;
    for (int e = t; e < 4096; e += 256){ Ws[e] = wsrc[e]; Xs[e] = xsrc[e]; }
    __syncthreads();
    int k = t & 63, rg = t >> 6;
    float acc[16];
    #pragma unroll
    for (int r = 0; r < 16; r++) acc[r] = 0.f;
    #pragma unroll 8
    for (int f = 0; f < 64; f++){
        float wf = Ws[f*64 + k];
        #pragma unroll
        for (int r = 0; r < 16; r++) acc[r] += Xs[(rg*16 + r)*64 + f] * wf;
    }
    float* fo = g_feats + ((b*4 + h)*2048 + it*64)*64;
    #pragma unroll
    for (int r = 0; r < 16; r++) fo[(rg*16 + r)*64 + k] = acc[r];
}

// ================= kernel 2: attention logit scalars =================
// warp per (b,h,n) row; 4096 blocks x 256
__global__ void __launch_bounds__(256) k_scores(const float* __restrict__ a_self,
                                                const float* __restrict__ a_neigh){
    int t = threadIdx.x, w = t >> 5, lane = t & 31;
    int row = blockIdx.x*8 + w;              // (b,h,n)
    int bh = row >> 11, h = bh & 3;
    const float* fr = g_feats + (size_t)row*64;
    float f0 = fr[lane], f1 = fr[lane + 32];
    float ss = f0*a_self[h*64 + lane]  + f1*a_self[h*64 + lane + 32];
    float sn = f0*a_neigh[h*64 + lane] + f1*a_neigh[h*64 + lane + 32];
    #pragma unroll
    for (int o = 16; o > 0; o >>= 1){
        ss += __shfl_xor_sync(0xffffffffu, ss, o);
        sn += __shfl_xor_sync(0xffffffffu, sn, o);
    }
    if (lane == 0){
        g_s_self[row]  = ss;
        g_s_neigh[row] = sn;
    }
}

// ================= kernel 3: Z = sum_j exp(score) per (b,h,i), no max pass =================
// block = 8 rows of one batch; warp per row; s_neigh staged head-major in smem.
// grid 1024 (= 4 b * 256 row-chunks), 256 threads
__global__ void __launch_bounds__(256) k_mz(const float* __restrict__ mask){
    __shared__ float snT[4][2048];
    int b = blockIdx.x >> 8, rc = blockIdx.x & 255;
    int t = threadIdx.x;
    for (int e = t; e < 8192; e += 256){
        int h = e >> 11, j = e & 2047;
        snT[h][j] = g_s_neigh[(b*4 + h)*2048 + j];
    }
    __syncthreads();
    int w = t >> 5, lane = t & 31;
    int i = rc*8 + w;
    float ss0 = g_s_self[(b*4+0)*2048 + i];
    float ss1 = g_s_self[(b*4+1)*2048 + i];
    float ss2 = g_s_self[(b*4+2)*2048 + i];
    float ss3 = g_s_self[(b*4+3)*2048 + i];
    const float4* mrow = (const float4*)(mask + ((size_t)b*2048 + i)*2048);
    float z0=0.f, z1=0.f, z2=0.f, z3=0.f;
    for (int jt = lane; jt < 512; jt += 32){
        float4 mk = mrow[jt];
        float4 s0 = *(const float4*)&snT[0][jt*4];
        float4 s1 = *(const float4*)&snT[1][jt*4];
        float4 s2 = *(const float4*)&snT[2][jt*4];
        float4 s3 = *(const float4*)&snT[3][jt*4];
        float sc;
        #define ONE(ssv, sv, mkc) { sc = ssv + sv; sc = sc > 0.f ? sc : 0.2f*sc; sc += mkc; }
        ONE(ss0, s0.x, mk.x); z0 += __expf(sc);  ONE(ss0, s0.y, mk.y); z0 += __expf(sc);
        ONE(ss0, s0.z, mk.z); z0 += __expf(sc);  ONE(ss0, s0.w, mk.w); z0 += __expf(sc);
        ONE(ss1, s1.x, mk.x); z1 += __expf(sc);  ONE(ss1, s1.y, mk.y); z1 += __expf(sc);
        ONE(ss1, s1.z, mk.z); z1 += __expf(sc);  ONE(ss1, s1.w, mk.w); z1 += __expf(sc);
        ONE(ss2, s2.x, mk.x); z2 += __expf(sc);  ONE(ss2, s2.y, mk.y); z2 += __expf(sc);
        ONE(ss2, s2.z, mk.z); z2 += __expf(sc);  ONE(ss2, s2.w, mk.w); z2 += __expf(sc);
        ONE(ss3, s3.x, mk.x); z3 += __expf(sc);  ONE(ss3, s3.y, mk.y); z3 += __expf(sc);
        ONE(ss3, s3.z, mk.z); z3 += __expf(sc);  ONE(ss3, s3.w, mk.w); z3 += __expf(sc);
        #undef ONE
    }
    #pragma unroll
    for (int o = 16; o > 0; o >>= 1){
        z0 += __shfl_xor_sync(0xffffffffu, z0, o);
        z1 += __shfl_xor_sync(0xffffffffu, z1, o);
        z2 += __shfl_xor_sync(0xffffffffu, z2, o);
        z3 += __shfl_xor_sync(0xffffffffu, z3, o);
    }
    if (lane == 0){
        g_invZ[(b*4+0)*2048 + i] = 1.f/z0;
        g_invZ[(b*4+1)*2048 + i] = 1.f/z1;
        g_invZ[(b*4+2)*2048 + i] = 1.f/z2;
        g_invZ[(b*4+3)*2048 + i] = 1.f/z3;
    }
}

// ================= kernel 4: P = softmax*adj ; partial += P @ feats =================
// grid (64, 4, 4): x = js*16 + it (j-split x i-tile-128), y=h, z=b; 256 threads
// thread GEMM tile: 8i (4 f32x2 pairs) x 4k
__global__ void __launch_bounds__(256, 3) k_main(const float* __restrict__ adj,
                                                 const float* __restrict__ mask){
    __shared__ float Ps[32*130];   // [j][i] pad 130
    __shared__ float Fs[32*64];    // [j][k]
    __shared__ float Ss[128], Zsm[128];
    __shared__ float rS[256];
    __shared__ int   rD[256], rA[256];

    int b = blockIdx.z, h = blockIdx.y;
    int js = blockIdx.x >> 4, it = blockIdx.x & 15;
    int t = threadIdx.x;
    int bh = b*4 + h;
    if (t < 128){
        int gi = it*128 + t;
        Ss[t]  = g_s_self[bh*2048 + gi];
        Zsm[t] = g_invZ[bh*2048 + gi];
    }
    int kg = t & 15, ig = t >> 4;
    int k0 = kg*4,  i0 = ig*8;
    u64 acc[4][4];
    #pragma unroll
    for (int a = 0; a < 4; a++)
        #pragma unroll
        for (int c = 0; c < 4; c++) acc[a][c] = 0ull;

    int jl = t & 31, ib = t >> 5;          // phase-A role: j-lane, i-pair group
    float sumD = 0.f; int cntD = 0, cntA = 0;
    const float* fbase = g_feats + (size_t)bh*2048*64;
    int jbase = js*512;

    for (int jt = 0; jt < 16; jt++){
        int j0 = jbase + jt*32;
        __syncthreads();
        // ---- Phase A: P tile (128 x 32) as i-pairs, loss stats ----
        float snj = g_s_neigh[bh*2048 + j0 + jl];
        #pragma unroll 4
        for (int p = 0; p < 8; p++){
            int i  = (p*8 + ib)*2;                   // even row 0..126
            int gi = it*128 + i;
            int gidx = (b*2048 + gi)*2048 + j0 + jl;
            float mk0 = mask[gidx], mk1 = mask[gidx + 2048];
            float aj0 = adj[gidx],  aj1 = adj[gidx + 2048];
            float sc0 = Ss[i]   + snj; sc0 = sc0 > 0.f ? sc0 : 0.2f*sc0; sc0 += mk0;
            float sc1 = Ss[i+1] + snj; sc1 = sc1 > 0.f ? sc1 : 0.2f*sc1; sc1 += mk1;
            float pd0 = __expf(sc0) * Zsm[i]   * aj0;
            float pd1 = __expf(sc1) * Zsm[i+1] * aj1;
            *(u64*)&Ps[jl*130 + i] = pk2(pd0, pd1);
            sumD += pd0 + pd1;
            cntD += (pd0 != 0.f) + (pd1 != 0.f);
            cntA += (aj0 != 0.f) + (aj1 != 0.f);
        }
        // ---- feats tile ----
        const float4* fsrc = (const float4*)(fbase + (size_t)j0*64);
        ((float4*)Fs)[t]       = fsrc[t];
        ((float4*)Fs)[t + 256] = fsrc[t + 256];
        __syncthreads();
        // ---- Phase B: FFMA2 GEMM ----
        #pragma unroll 8
        for (int j = 0; j < 32; j++){
            float4 v = *(const float4*)&Fs[j*64 + k0];
            u64 v0 = pk2(v.x, v.x), v1 = pk2(v.y, v.y);
            u64 v2 = pk2(v.z, v.z), v3 = pk2(v.w, v.w);
            const float* pr = &Ps[j*130 + i0];
            u64 p0 = *(const u64*)(pr);
            u64 p1 = *(const u64*)(pr + 2);
            u64 p2 = *(const u64*)(pr + 4);
            u64 p3 = *(const u64*)(pr + 6);
            fma2(acc[0][0], p0, v0); fma2(acc[0][1], p0, v1); fma2(acc[0][2], p0, v2); fma2(acc[0][3], p0, v3);
            fma2(acc[1][0], p1, v0); fma2(acc[1][1], p1, v1); fma2(acc[1][2], p1, v2); fma2(acc[1][3], p1, v3);
            fma2(acc[2][0], p2, v0); fma2(acc[2][1], p2, v1); fma2(acc[2][2], p2, v2); fma2(acc[2][3], p2, v3);
            fma2(acc[3][0], p3, v0); fma2(acc[3][1], p3, v1); fma2(acc[3][2], p3, v2); fma2(acc[3][3], p3, v3);
        }
    }

    // ---- write partial (no bias/relu yet) ----
    float* po = g_part + (size_t)js*OUTEL;
    #pragma unroll
    for (int ip = 0; ip < 4; ip++){
        float2 e0 = upk(acc[ip][0]), e1 = upk(acc[ip][1]);
        float2 e2 = upk(acc[ip][2]), e3 = upk(acc[ip][3]);
        int r0 = it*128 + i0 + 2*ip;
        float4 o0 = {e0.x, e1.x, e2.x, e3.x};
        float4 o1 = {e0.y, e1.y, e2.y, e3.y};
        *(float4*)&po[(size_t)(b*2048 + r0    )*256 + h*64 + k0] = o0;
        *(float4*)&po[(size_t)(b*2048 + r0 + 1)*256 + h*64 + k0] = o1;
    }

    // ---- deterministic block reduce of loss stats ----
    rS[t] = sumD; rD[t] = cntD; rA[t] = cntA;
    __syncthreads();
    #pragma unroll
    for (int s = 128; s > 0; s >>= 1){
        if (t < s){ rS[t] += rS[t + s]; rD[t] += rD[t + s]; rA[t] += rA[t + s]; }
        __syncthreads();
    }
    if (t == 0){
        int pb = ((bh*16 + it)*4) + js;
        g_psum[pb] = rS[0]; g_pcd[pb] = rD[0]; g_pca[pb] = rA[0];
    }
}

// ================= kernel 5: combine partials + bias + BN + relu =================
// grid 2048 x 256; thread per float4
__global__ void __launch_bounds__(256) k_epi(const float* __restrict__ bias,
                                             float* __restrict__ out){
    const float SC = 0.9995003746877732f;   // 1/sqrt(1.001)
    int idx = blockIdx.x*256 + threadIdx.x;            // float4 index
    int hk = (idx*4) & 255;                            // h*64 + k
    const float4* p = (const float4*)g_part;
    float4 s0 = p[idx];
    float4 s1 = p[idx +   OUTEL/4];
    float4 s2 = p[idx + 2*OUTEL/4];
    float4 s3 = p[idx + 3*OUTEL/4];
    float4 bi = *(const float4*)&bias[hk];
    float4 o;
    o.x = fmaxf((s0.x + s1.x + s2.x + s3.x + bi.x)*SC, 0.f);
    o.y = fmaxf((s0.y + s1.y + s2.y + s3.y + bi.y)*SC, 0.f);
    o.z = fmaxf((s0.z + s1.z + s2.z + s3.z + bi.z)*SC, 0.f);
    o.w = fmaxf((s0.w + s1.w + s2.w + s3.w + bi.w)*SC, 0.f);
    ((float4*)out)[idx] = o;
}

// ================= kernel 6: finalize aux losses =================
__global__ void k_loss(float* __restrict__ out){
    int b = threadIdx.x;
    if (b < 4){
        float s = 0.f; int d = 0, a = 0;
        for (int p = 0; p < 256; p++){
            int idx = b*256 + p;
            s += g_psum[idx]; d += g_pcd[idx]; a += g_pca[idx];
        }
        out[OUTEL + b]     = (float)(d - a) * (1.f/2048.f);
        out[OUTEL + 4 + b] = s * (1.f/2048.f);
    }
}

// ================= launch =================
extern "C" void kernel_launch(void* const* d_in, const int* in_sizes, int n_in,
                              void* d_out, int out_size){
    const float* x       = (const float*)d_in[0];
    const float* adj     = (const float*)d_in[1];
    const float* mask    = (const float*)d_in[2];
    const float* W       = (const float*)d_in[3];
    const float* a_self  = (const float*)d_in[4];
    const float* a_neigh = (const float*)d_in[5];
    const float* bias    = (const float*)d_in[6];
    float* out = (float*)d_out;

    k_feats <<<dim3(32, 4, 4), 256>>>(x, W);
    k_scores<<<4096, 256>>>(a_self, a_neigh);
    k_mz    <<<1024, 256>>>(mask);
    k_main  <<<dim3(64, 4, 4), 256>>>(adj, mask);
    k_epi   <<<2048, 256>>>(bias, out);
    k_loss  <<<1, 32>>>(out);
}

// round 3
// speedup vs baseline: 1.3102x; 1.0120x over previous
#include <cuda_runtime.h>
#include <math.h>

typedef unsigned long long u64;
#define DINL __device__ __forceinline__

#define JSPLIT 4
#define OUTEL  2097152            // 4*2048*256

// ---------------- scratch (no allocations allowed) ----------------
static __device__ float  g_feats[4*4*2048*64];     // [b][h][n][64]  8 MB
static __device__ float  g_s_self[4*4*2048];
static __device__ float  g_s_neigh[4*4*2048];
static __device__ float  g_invZ[4*4*2048];
static __device__ float  g_part[JSPLIT*OUTEL];     // 33.5 MB partial outputs
static __device__ float  g_psum[1024];
static __device__ int    g_pcd[1024];
static __device__ int    g_pca[1024];

// ---------------- f32x2 helpers ----------------
DINL u64 pk2(float a, float b){ u64 r; asm("mov.b64 %0, {%1, %2};" : "=l"(r) : "f"(a), "f"(b)); return r; }
DINL void fma2(u64& d, u64 a, u64 b){ asm("fma.rn.f32x2 %0, %1, %2, %0;" : "+l"(d) : "l"(a), "l"(b)); }
DINL float2 upk(u64 v){ float2 r; asm("mov.b64 {%0, %1}, %2;" : "=f"(r.x), "=f"(r.y) : "l"(v)); return r; }

// ================= kernel 1: feats = x @ W[h] =================
// grid (32, 4, 4) = (ntile64, h, b), 256 threads
__global__ void __launch_bounds__(256) k_feats(const float* __restrict__ x,
                                               const float* __restrict__ W){
    __shared__ float Ws[64*64];
    __shared__ float Xs[64*64];
    int b = blockIdx.z, h = blockIdx.y, it = blockIdx.x, t = threadIdx.x;
    const float* wsrc = W + h*4096;
    const float* xsrc = x + (b*2048 + it*64)*64;
    for (int e = t; e < 4096; e += 256){ Ws[e] = wsrc[e]; Xs[e] = xsrc[e]; }
    __syncthreads();
    int k = t & 63, rg = t >> 6;
    float acc[16];
    #pragma unroll
    for (int r = 0; r < 16; r++) acc[r] = 0.f;
    #pragma unroll 8
    for (int f = 0; f < 64; f++){
        float wf = Ws[f*64 + k];
        #pragma unroll
        for (int r = 0; r < 16; r++) acc[r] += Xs[(rg*16 + r)*64 + f] * wf;
    }
    float* fo = g_feats + ((b*4 + h)*2048 + it*64)*64;
    #pragma unroll
    for (int r = 0; r < 16; r++) fo[(rg*16 + r)*64 + k] = acc[r];
}

// ================= kernel 2: attention logit scalars =================
// warp per (b,h,n) row; 4096 blocks x 256
__global__ void __launch_bounds__(256) k_scores(const float* __restrict__ a_self,
                                                const float* __restrict__ a_neigh){
    int t = threadIdx.x, w = t >> 5, lane = t & 31;
    int row = blockIdx.x*8 + w;              // (b,h,n)
    int bh = row >> 11, h = bh & 3;
    const float* fr = g_feats + (size_t)row*64;
    float f0 = fr[lane], f1 = fr[lane + 32];
    float ss = f0*a_self[h*64 + lane]  + f1*a_self[h*64 + lane + 32];
    float sn = f0*a_neigh[h*64 + lane] + f1*a_neigh[h*64 + lane + 32];
    #pragma unroll
    for (int o = 16; o > 0; o >>= 1){
        ss += __shfl_xor_sync(0xffffffffu, ss, o);
        sn += __shfl_xor_sync(0xffffffffu, sn, o);
    }
    if (lane == 0){
        g_s_self[row]  = ss;
        g_s_neigh[row] = sn;
    }
}

// ================= kernel 3: Z = sum_j exp(score) per (b,h,i), no max pass =================
// block = 8 rows of one batch; warp per row; s_neigh staged head-major in smem.
// grid 1024 (= 4 b * 256 row-chunks), 256 threads
__global__ void __launch_bounds__(256) k_mz(const float* __restrict__ mask){
    __shared__ float snT[4][2048];
    int b = blockIdx.x >> 8, rc = blockIdx.x & 255;
    int t = threadIdx.x;
    for (int e = t; e < 8192; e += 256){
        int h = e >> 11, j = e & 2047;
        snT[h][j] = g_s_neigh[(b*4 + h)*2048 + j];
    }
    __syncthreads();
    int w = t >> 5, lane = t & 31;
    int i = rc*8 + w;
    float ss0 = g_s_self[(b*4+0)*2048 + i];
    float ss1 = g_s_self[(b*4+1)*2048 + i];
    float ss2 = g_s_self[(b*4+2)*2048 + i];
    float ss3 = g_s_self[(b*4+3)*2048 + i];
    const float4* mrow = (const float4*)(mask + ((size_t)b*2048 + i)*2048);
    float z0=0.f, z1=0.f, z2=0.f, z3=0.f;
    for (int jt = lane; jt < 512; jt += 32){
        float4 mk = mrow[jt];
        float4 s0 = *(const float4*)&snT[0][jt*4];
        float4 s1 = *(const float4*)&snT[1][jt*4];
        float4 s2 = *(const float4*)&snT[2][jt*4];
        float4 s3 = *(const float4*)&snT[3][jt*4];
        float sc;
        #define ONE(ssv, sv, mkc) { sc = ssv + sv; sc = sc > 0.f ? sc : 0.2f*sc; sc += mkc; }
        ONE(ss0, s0.x, mk.x); z0 += __expf(sc);  ONE(ss0, s0.y, mk.y); z0 += __expf(sc);
        ONE(ss0, s0.z, mk.z); z0 += __expf(sc);  ONE(ss0, s0.w, mk.w); z0 += __expf(sc);
        ONE(ss1, s1.x, mk.x); z1 += __expf(sc);  ONE(ss1, s1.y, mk.y); z1 += __expf(sc);
        ONE(ss1, s1.z, mk.z); z1 += __expf(sc);  ONE(ss1, s1.w, mk.w); z1 += __expf(sc);
        ONE(ss2, s2.x, mk.x); z2 += __expf(sc);  ONE(ss2, s2.y, mk.y); z2 += __expf(sc);
        ONE(ss2, s2.z, mk.z); z2 += __expf(sc);  ONE(ss2, s2.w, mk.w); z2 += __expf(sc);
        ONE(ss3, s3.x, mk.x); z3 += __expf(sc);  ONE(ss3, s3.y, mk.y); z3 += __expf(sc);
        ONE(ss3, s3.z, mk.z); z3 += __expf(sc);  ONE(ss3, s3.w, mk.w); z3 += __expf(sc);
        #undef ONE
    }
    #pragma unroll
    for (int o = 16; o > 0; o >>= 1){
        z0 += __shfl_xor_sync(0xffffffffu, z0, o);
        z1 += __shfl_xor_sync(0xffffffffu, z1, o);
        z2 += __shfl_xor_sync(0xffffffffu, z2, o);
        z3 += __shfl_xor_sync(0xffffffffu, z3, o);
    }
    if (lane == 0){
        g_invZ[(b*4+0)*2048 + i] = 1.f/z0;
        g_invZ[(b*4+1)*2048 + i] = 1.f/z1;
        g_invZ[(b*4+2)*2048 + i] = 1.f/z2;
        g_invZ[(b*4+3)*2048 + i] = 1.f/z3;
    }
}

// ================= kernel 4: P = softmax*adj ; partial += P @ feats =================
// grid (64, 4, 4): x = js*16 + it (j-split x i-tile-128), y=h, z=b; 256 threads
// thread GEMM tile: 8i (4 f32x2 pairs) x 4k
__global__ void __launch_bounds__(256, 3) k_main(const float* __restrict__ adj,
                                                 const float* __restrict__ mask){
    __shared__ float Ps[32*130];   // [j][i] pad 130
    __shared__ float Fs[32*64];    // [j][k]
    __shared__ float Ss[128], Zsm[128];
    __shared__ float rS[256];
    __shared__ int   rD[256], rA[256];

    int b = blockIdx.z, h = blockIdx.y;
    int js = blockIdx.x >> 4, it = blockIdx.x & 15;
    int t = threadIdx.x;
    int bh = b*4 + h;
    if (t < 128){
        int gi = it*128 + t;
        Ss[t]  = g_s_self[bh*2048 + gi];
        Zsm[t] = g_invZ[bh*2048 + gi];
    }
    int kg = t & 15, ig = t >> 4;
    int k0 = kg*4,  i0 = ig*8;
    u64 acc[4][4];
    #pragma unroll
    for (int a = 0; a < 4; a++)
        #pragma unroll
        for (int c = 0; c < 4; c++) acc[a][c] = 0ull;

    int jl = t & 31, ib = t >> 5;          // phase-A role: j-lane, i-pair group
    float sumD = 0.f; int cntD = 0, cntA = 0;
    const float* fbase = g_feats + (size_t)bh*2048*64;
    int jbase = js*512;

    for (int jt = 0; jt < 16; jt++){
        int j0 = jbase + jt*32;
        __syncthreads();
        // ---- Phase A: P tile (128 x 32) as i-pairs, loss stats ----
        float snj = g_s_neigh[bh*2048 + j0 + jl];
        #pragma unroll 4
        for (int p = 0; p < 8; p++){
            int i  = (p*8 + ib)*2;                   // even row 0..126
            int gi = it*128 + i;
            int gidx = (b*2048 + gi)*2048 + j0 + jl;
            float mk0 = mask[gidx], mk1 = mask[gidx + 2048];
            float aj0 = adj[gidx],  aj1 = adj[gidx + 2048];
            float sc0 = Ss[i]   + snj; sc0 = sc0 > 0.f ? sc0 : 0.2f*sc0; sc0 += mk0;
            float sc1 = Ss[i+1] + snj; sc1 = sc1 > 0.f ? sc1 : 0.2f*sc1; sc1 += mk1;
            float pd0 = __expf(sc0) * Zsm[i]   * aj0;
            float pd1 = __expf(sc1) * Zsm[i+1] * aj1;
            *(u64*)&Ps[jl*130 + i] = pk2(pd0, pd1);
            sumD += pd0 + pd1;
            cntD += (pd0 != 0.f) + (pd1 != 0.f);
            cntA += (aj0 != 0.f) + (aj1 != 0.f);
        }
        // ---- feats tile ----
        const float4* fsrc = (const float4*)(fbase + (size_t)j0*64);
        ((float4*)Fs)[t]       = fsrc[t];
        ((float4*)Fs)[t + 256] = fsrc[t + 256];
        __syncthreads();
        // ---- Phase B: FFMA2 GEMM ----
        #pragma unroll 8
        for (int j = 0; j < 32; j++){
            float4 v = *(const float4*)&Fs[j*64 + k0];
            u64 v0 = pk2(v.x, v.x), v1 = pk2(v.y, v.y);
            u64 v2 = pk2(v.z, v.z), v3 = pk2(v.w, v.w);
            const float* pr = &Ps[j*130 + i0];
            u64 p0 = *(const u64*)(pr);
            u64 p1 = *(const u64*)(pr + 2);
            u64 p2 = *(const u64*)(pr + 4);
            u64 p3 = *(const u64*)(pr + 6);
            fma2(acc[0][0], p0, v0); fma2(acc[0][1], p0, v1); fma2(acc[0][2], p0, v2); fma2(acc[0][3], p0, v3);
            fma2(acc[1][0], p1, v0); fma2(acc[1][1], p1, v1); fma2(acc[1][2], p1, v2); fma2(acc[1][3], p1, v3);
            fma2(acc[2][0], p2, v0); fma2(acc[2][1], p2, v1); fma2(acc[2][2], p2, v2); fma2(acc[2][3], p2, v3);
            fma2(acc[3][0], p3, v0); fma2(acc[3][1], p3, v1); fma2(acc[3][2], p3, v2); fma2(acc[3][3], p3, v3);
        }
    }

    // ---- write partial (no bias/relu yet) ----
    float* po = g_part + (size_t)js*OUTEL;
    #pragma unroll
    for (int ip = 0; ip < 4; ip++){
        float2 e0 = upk(acc[ip][0]), e1 = upk(acc[ip][1]);
        float2 e2 = upk(acc[ip][2]), e3 = upk(acc[ip][3]);
        int r0 = it*128 + i0 + 2*ip;
        float4 o0 = {e0.x, e1.x, e2.x, e3.x};
        float4 o1 = {e0.y, e1.y, e2.y, e3.y};
        *(float4*)&po[(size_t)(b*2048 + r0    )*256 + h*64 + k0] = o0;
        *(float4*)&po[(size_t)(b*2048 + r0 + 1)*256 + h*64 + k0] = o1;
    }

    // ---- deterministic block reduce of loss stats ----
    rS[t] = sumD; rD[t] = cntD; rA[t] = cntA;
    __syncthreads();
    #pragma unroll
    for (int s = 128; s > 0; s >>= 1){
        if (t < s){ rS[t] += rS[t + s]; rD[t] += rD[t + s]; rA[t] += rA[t + s]; }
        __syncthreads();
    }
    if (t == 0){
        int pb = ((bh*16 + it)*4) + js;
        g_psum[pb] = rS[0]; g_pcd[pb] = rD[0]; g_pca[pb] = rA[0];
    }
}

// ================= kernel 5: combine partials + bias + BN + relu =================
// grid 2048 x 256; thread per float4
__global__ void __launch_bounds__(256) k_epi(const float* __restrict__ bias,
                                             float* __restrict__ out){
    const float SC = 0.9995003746877732f;   // 1/sqrt(1.001)
    int idx = blockIdx.x*256 + threadIdx.x;            // float4 index
    int hk = (idx*4) & 255;                            // h*64 + k
    const float4* p = (const float4*)g_part;
    float4 s0 = p[idx];
    float4 s1 = p[idx +   OUTEL/4];
    float4 s2 = p[idx + 2*OUTEL/4];
    float4 s3 = p[idx + 3*OUTEL/4];
    float4 bi = *(const float4*)&bias[hk];
    float4 o;
    o.x = fmaxf((s0.x + s1.x + s2.x + s3.x + bi.x)*SC, 0.f);
    o.y = fmaxf((s0.y + s1.y + s2.y + s3.y + bi.y)*SC, 0.f);
    o.z = fmaxf((s0.z + s1.z + s2.z + s3.z + bi.z)*SC, 0.f);
    o.w = fmaxf((s0.w + s1.w + s2.w + s3.w + bi.w)*SC, 0.f);
    ((float4*)out)[idx] = o;
}

// ================= kernel 6: finalize aux losses =================
__global__ void k_loss(float* __restrict__ out){
    int b = threadIdx.x;
    if (b < 4){
        float s = 0.f; int d = 0, a = 0;
        for (int p = 0; p < 256; p++){
            int idx = b*256 + p;
            s += g_psum[idx]; d += g_pcd[idx]; a += g_pca[idx];
        }
        out[OUTEL + b]     = (float)(d - a) * (1.f/2048.f);
        out[OUTEL + 4 + b] = s * (1.f/2048.f);
    }
}

// ================= launch =================
extern "C" void kernel_launch(void* const* d_in, const int* in_sizes, int n_in,
                              void* d_out, int out_size){
    const float* x       = (const float*)d_in[0];
    const float* adj     = (const float*)d_in[1];
    const float* mask    = (const float*)d_in[2];
    const float* W       = (const float*)d_in[3];
    const float* a_self  = (const float*)d_in[4];
    const float* a_neigh = (const float*)d_in[5];
    const float* bias    = (const float*)d_in[6];
    float* out = (float*)d_out;

    k_feats <<<dim3(32, 4, 4), 256>>>(x, W);
    k_scores<<<4096, 256>>>(a_self, a_neigh);
    k_mz    <<<1024, 256>>>(mask);
    k_main  <<<dim3(64, 4, 4), 256>>>(adj, mask);
    k_epi   <<<2048, 256>>>(bias, out);
    k_loss  <<<1, 32>>>(out);
}

// round 4
// speedup vs baseline: 1.5861x; 1.2106x over previous
#include <cuda_runtime.h>
#include <math.h>

typedef unsigned long long u64;
#define DINL __device__ __forceinline__

#define JSPLIT 4
#define OUTEL  2097152            // 4*2048*256

// ---------------- scratch ----------------
static __device__ float g_feats[4*4*2048*64];     // [b][h][n][64]
static __device__ float g_ss [32768];             // [bh][n] self score
static __device__ float g_Fa [32768];             // e^{sn}
static __device__ float g_Fb [32768];             // e^{0.2 sn}
static __device__ float g_thr[32768];             // e^{-ss}
static __device__ float g_EaZ[32768];             // e^{ss}/z
static __device__ float g_EbZ[32768];             // e^{0.2 ss}/z
static __device__ float g_part[JSPLIT*OUTEL];
static __device__ float g_psum[1024];
static __device__ int   g_pcd[1024];
static __device__ int   g_pca[1024];
static __device__ int   g_mflag;                  // nonzero-mask flag

// ---------------- f32x2 helpers ----------------
DINL u64 pk2(float a, float b){ u64 r; asm("mov.b64 %0, {%1, %2};" : "=l"(r) : "f"(a), "f"(b)); return r; }
DINL void fma2(u64& d, u64 a, u64 b){ asm("fma.rn.f32x2 %0, %1, %2, %0;" : "+l"(d) : "l"(a), "l"(b)); }
DINL float2 upk(u64 v){ float2 r; asm("mov.b64 {%0, %1}, %2;" : "=f"(r.x), "=f"(r.y) : "l"(v)); return r; }

// ================= kernel 1: feats = x @ W[h] =================
__global__ void __launch_bounds__(256) k_feats(const float* __restrict__ x,
                                               const float* __restrict__ W){
    __shared__ float Ws[64*64];
    __shared__ float Xs[64*64];
    int b = blockIdx.z, h = blockIdx.y, it = blockIdx.x, t = threadIdx.x;
    if (b == 0 && h == 0 && it == 0 && t == 0) g_mflag = 0;   // per-launch reset
    const float* wsrc = W + h*4096;
    const float* xsrc = x + (b*2048 + it*64)*64;
    for (int e = t; e < 4096; e += 256){ Ws[e] = wsrc[e]; Xs[e] = xsrc[e]; }
    __syncthreads();
    int k = t & 63, rg = t >> 6;
    float acc[16];
    #pragma unroll
    for (int r = 0; r < 16; r++) acc[r] = 0.f;
    #pragma unroll 8
    for (int f = 0; f < 64; f++){
        float wf = Ws[f*64 + k];
        #pragma unroll
        for (int r = 0; r < 16; r++) acc[r] += Xs[(rg*16 + r)*64 + f] * wf;
    }
    float* fo = g_feats + ((b*4 + h)*2048 + it*64)*64;
    #pragma unroll
    for (int r = 0; r < 16; r++) fo[(rg*16 + r)*64 + k] = acc[r];
}

// ================= kernel 2: scores + factorized exps =================
__global__ void __launch_bounds__(256) k_scores(const float* __restrict__ a_self,
                                                const float* __restrict__ a_neigh){
    int t = threadIdx.x, w = t >> 5, lane = t & 31;
    int row = blockIdx.x*8 + w;              // (b,h,n)
    int bh = row >> 11, h = bh & 3;
    const float* fr = g_feats + (size_t)row*64;
    float f0 = fr[lane], f1 = fr[lane + 32];
    float ss = f0*a_self[h*64 + lane]  + f1*a_self[h*64 + lane + 32];
    float sn = f0*a_neigh[h*64 + lane] + f1*a_neigh[h*64 + lane + 32];
    #pragma unroll
    for (int o = 16; o > 0; o >>= 1){
        ss += __shfl_xor_sync(0xffffffffu, ss, o);
        sn += __shfl_xor_sync(0xffffffffu, sn, o);
    }
    if (lane == 0){
        g_ss[row] = ss;
        g_Fa[row] = __expf(sn);
        g_Fb[row] = __expf(0.2f*sn);
    }
}

// ================= kernel 3: Z per (b,h,i) via factorization; mask flag =================
// warp per (b,i) row, all 4 heads; Fa/Fb staged in smem in two j-halves.
// grid 1024 = 4b * 256 rowchunks, 256 threads
__global__ void __launch_bounds__(256) k_mz(const float* __restrict__ mask){
    __shared__ float FaT[4][1024];
    __shared__ float FbT[4][1024];
    int b = blockIdx.x >> 8, rc = blockIdx.x & 255;
    int t = threadIdx.x, w = t >> 5, lane = t & 31;
    int i = rc*8 + w;
    float ss[4], thr[4];
    float zA[4] = {0,0,0,0}, zB[4] = {0,0,0,0};
    #pragma unroll
    for (int h = 0; h < 4; h++){
        ss[h]  = g_ss[(b*4 + h)*2048 + i];
        thr[h] = __expf(-ss[h]);
    }
    const float4* mrow = (const float4*)(mask + ((size_t)b*2048 + i)*2048);
    bool anym = false;
    for (int half = 0; half < 2; half++){
        __syncthreads();
        for (int e = t; e < 4096; e += 256){
            int h = e >> 10, j = e & 1023;
            FaT[h][j] = g_Fa[(b*4 + h)*2048 + half*1024 + j];
            FbT[h][j] = g_Fb[(b*4 + h)*2048 + half*1024 + j];
        }
        __syncthreads();
        for (int q = lane; q < 256; q += 32){
            float4 mk = mrow[half*256 + q];
            float e0 = 1.f, e1 = 1.f, e2 = 1.f, e3 = 1.f;
            if (mk.x != 0.f){ e0 = __expf(mk.x); anym = true; }
            if (mk.y != 0.f){ e1 = __expf(mk.y); anym = true; }
            if (mk.z != 0.f){ e2 = __expf(mk.z); anym = true; }
            if (mk.w != 0.f){ e3 = __expf(mk.w); anym = true; }
            #pragma unroll
            for (int h = 0; h < 4; h++){
                float4 fa = *(const float4*)&FaT[h][q*4];
                float4 fb = *(const float4*)&FbT[h][q*4];
                if (fa.x > thr[h]) zA[h] += fa.x*e0; else zB[h] += fb.x*e0;
                if (fa.y > thr[h]) zA[h] += fa.y*e1; else zB[h] += fb.y*e1;
                if (fa.z > thr[h]) zA[h] += fa.z*e2; else zB[h] += fb.z*e2;
                if (fa.w > thr[h]) zA[h] += fa.w*e3; else zB[h] += fb.w*e3;
            }
        }
    }
    #pragma unroll
    for (int o = 16; o > 0; o >>= 1){
        #pragma unroll
        for (int h = 0; h < 4; h++){
            zA[h] += __shfl_xor_sync(0xffffffffu, zA[h], o);
            zB[h] += __shfl_xor_sync(0xffffffffu, zB[h], o);
        }
    }
    if (lane == 0){
        #pragma unroll
        for (int h = 0; h < 4; h++){
            float Ea = __expf(ss[h]), Eb = __expf(0.2f*ss[h]);
            float z = Ea*zA[h] + Eb*zB[h];
            int idx = (b*4 + h)*2048 + i;
            g_thr[idx] = thr[h];
            g_EaZ[idx] = Ea / z;
            g_EbZ[idx] = Eb / z;
        }
    }
    if (anym) atomicOr(&g_mflag, 1);
}

// ================= kernel 4: P = factorized softmax * adj ; partial = P @ feats =================
// grid (64,4,4): x = js*16+it, y=h, z=b; 256 threads; thread tile 8i(4 f32x2) x 4k
__global__ void __launch_bounds__(256, 4) k_main(const float* __restrict__ adj,
                                                 const float* __restrict__ mask){
    __shared__ float Ps[32*130];     // [j][i] pad 130
    __shared__ float Fs[32*64];      // [j][k]
    __shared__ float FaS[512], FbS[512];
    __shared__ float thrS[128], EaZS[128], EbZS[128];
    __shared__ float rS[256];
    __shared__ int   rD[256], rA[256];

    int b = blockIdx.z, h = blockIdx.y;
    int js = blockIdx.x >> 4, it = blockIdx.x & 15;
    int t = threadIdx.x;
    int bh = b*4 + h;
    int jbase = js*512;
    for (int e = t; e < 512; e += 256){
        FaS[e] = g_Fa[bh*2048 + jbase + e];
        FbS[e] = g_Fb[bh*2048 + jbase + e];
    }
    if (t < 128){
        int gi = bh*2048 + it*128 + t;
        thrS[t] = g_thr[gi]; EaZS[t] = g_EaZ[gi]; EbZS[t] = g_EbZ[gi];
    }
    const bool mz = (g_mflag == 0);

    int kg = t & 15, ig = t >> 4;
    int k0 = kg*4,  i0 = ig*8;
    u64 acc[4][4];
    #pragma unroll
    for (int a = 0; a < 4; a++)
        #pragma unroll
        for (int c = 0; c < 4; c++) acc[a][c] = 0ull;

    int jl = t & 31, ib = t >> 5;
    float sumD = 0.f; int cntD = 0, cntA = 0;
    const float* fbase = g_feats + (size_t)bh*2048*64;
    int rowbase = (b*2048 + it*128)*2048 + jbase + jl;   // + i*2048 + jt*32

    #pragma unroll 1
    for (int jt = 0; jt < 16; jt++){
        __syncthreads();
        // ---- Phase A: factorized P tile (128 x 32) ----
        float fa = FaS[jt*32 + jl];
        float fb = FbS[jt*32 + jl];
        int gb = rowbase + jt*32;
        #pragma unroll
        for (int p = 0; p < 8; p++){
            int i = (p*8 + ib)*2;
            int gidx = gb + i*2048;
            float a0 = adj[gidx], a1 = adj[gidx + 2048];
            float w0 = (fa > thrS[i]  ) ? EaZS[i]  *fa : EbZS[i]  *fb;
            float w1 = (fa > thrS[i+1]) ? EaZS[i+1]*fa : EbZS[i+1]*fb;
            float pd0 = a0 * w0;
            float pd1 = a1 * w1;
            if (!mz){                       // general-mask fallback (never taken when mask==0)
                pd0 *= __expf(mask[gidx]);
                pd1 *= __expf(mask[gidx + 2048]);
            }
            *(u64*)&Ps[jl*130 + i] = pk2(pd0, pd1);
            sumD += fabsf(pd0) + fabsf(pd1);
            cntD += (pd0 != 0.f) + (pd1 != 0.f);
            cntA += (a0  != 0.f) + (a1  != 0.f);
        }
        // ---- feats tile ----
        const float4* fsrc = (const float4*)(fbase + (size_t)(jbase + jt*32)*64);
        ((float4*)Fs)[t]       = fsrc[t];
        ((float4*)Fs)[t + 256] = fsrc[t + 256];
        __syncthreads();
        // ---- Phase B: FFMA2 GEMM ----
        #pragma unroll 8
        for (int j = 0; j < 32; j++){
            float4 v = *(const float4*)&Fs[j*64 + k0];
            u64 v0 = pk2(v.x, v.x), v1 = pk2(v.y, v.y);
            u64 v2 = pk2(v.z, v.z), v3 = pk2(v.w, v.w);
            const float* pr = &Ps[j*130 + i0];
            u64 p0 = *(const u64*)(pr);
            u64 p1 = *(const u64*)(pr + 2);
            u64 p2 = *(const u64*)(pr + 4);
            u64 p3 = *(const u64*)(pr + 6);
            fma2(acc[0][0], p0, v0); fma2(acc[0][1], p0, v1); fma2(acc[0][2], p0, v2); fma2(acc[0][3], p0, v3);
            fma2(acc[1][0], p1, v0); fma2(acc[1][1], p1, v1); fma2(acc[1][2], p1, v2); fma2(acc[1][3], p1, v3);
            fma2(acc[2][0], p2, v0); fma2(acc[2][1], p2, v1); fma2(acc[2][2], p2, v2); fma2(acc[2][3], p2, v3);
            fma2(acc[3][0], p3, v0); fma2(acc[3][1], p3, v1); fma2(acc[3][2], p3, v2); fma2(acc[3][3], p3, v3);
        }
    }

    // ---- write partial ----
    float* po = g_part + (size_t)js*OUTEL;
    #pragma unroll
    for (int ip = 0; ip < 4; ip++){
        float2 e0 = upk(acc[ip][0]), e1 = upk(acc[ip][1]);
        float2 e2 = upk(acc[ip][2]), e3 = upk(acc[ip][3]);
        int r0 = it*128 + i0 + 2*ip;
        float4 o0 = {e0.x, e1.x, e2.x, e3.x};
        float4 o1 = {e0.y, e1.y, e2.y, e3.y};
        *(float4*)&po[(size_t)(b*2048 + r0    )*256 + h*64 + k0] = o0;
        *(float4*)&po[(size_t)(b*2048 + r0 + 1)*256 + h*64 + k0] = o1;
    }

    // ---- deterministic block reduce of loss stats ----
    rS[t] = sumD; rD[t] = cntD; rA[t] = cntA;
    __syncthreads();
    #pragma unroll
    for (int s = 128; s > 0; s >>= 1){
        if (t < s){ rS[t] += rS[t + s]; rD[t] += rD[t + s]; rA[t] += rA[t + s]; }
        __syncthreads();
    }
    if (t == 0){
        int pb = ((bh*16 + it)*4) + js;
        g_psum[pb] = rS[0]; g_pcd[pb] = rD[0]; g_pca[pb] = rA[0];
    }
}

// ================= kernel 5: combine partials + bias + BN + relu =================
__global__ void __launch_bounds__(256) k_epi(const float* __restrict__ bias,
                                             float* __restrict__ out){
    const float SC = 0.9995003746877732f;   // 1/sqrt(1.001)
    int idx = blockIdx.x*256 + threadIdx.x;
    int hk = (idx*4) & 255;
    const float4* p = (const float4*)g_part;
    float4 s0 = p[idx];
    float4 s1 = p[idx +   OUTEL/4];
    float4 s2 = p[idx + 2*OUTEL/4];
    float4 s3 = p[idx + 3*OUTEL/4];
    float4 bi = *(const float4*)&bias[hk];
    float4 o;
    o.x = fmaxf((s0.x + s1.x + s2.x + s3.x + bi.x)*SC, 0.f);
    o.y = fmaxf((s0.y + s1.y + s2.y + s3.y + bi.y)*SC, 0.f);
    o.z = fmaxf((s0.z + s1.z + s2.z + s3.z + bi.z)*SC, 0.f);
    o.w = fmaxf((s0.w + s1.w + s2.w + s3.w + bi.w)*SC, 0.f);
    ((float4*)out)[idx] = o;
}

// ================= kernel 6: finalize aux losses =================
__global__ void k_loss(float* __restrict__ out){
    int b = threadIdx.x;
    if (b < 4){
        float s = 0.f; int d = 0, a = 0;
        for (int p = 0; p < 256; p++){
            int idx = b*256 + p;
            s += g_psum[idx]; d += g_pcd[idx]; a += g_pca[idx];
        }
        out[OUTEL + b]     = (float)(d - a) * (1.f/2048.f);
        out[OUTEL + 4 + b] = s * (1.f/2048.f);
    }
}

// ================= launch =================
extern "C" void kernel_launch(void* const* d_in, const int* in_sizes, int n_in,
                              void* d_out, int out_size){
    const float* x       = (const float*)d_in[0];
    const float* adj     = (const float*)d_in[1];
    const float* mask    = (const float*)d_in[2];
    const float* W       = (const float*)d_in[3];
    const float* a_self  = (const float*)d_in[4];
    const float* a_neigh = (const float*)d_in[5];
    const float* bias    = (const float*)d_in[6];
    float* out = (float*)d_out;

    k_feats <<<dim3(32, 4, 4), 256>>>(x, W);
    k_scores<<<4096, 256>>>(a_self, a_neigh);
    k_mz    <<<1024, 256>>>(mask);
    k_main  <<<dim3(64, 4, 4), 256>>>(adj, mask);
    k_epi   <<<2048, 256>>>(bias, out);
    k_loss  <<<1, 32>>>(out);
}